// round 4
// baseline (speedup 1.0000x reference)
#include <cuda_runtime.h>
#include <cstdint>

#define KK 1000
#define BB 64
#define MAXIT 50
#define NTHR 256
#define ROWS_PER 10

// ---------------- device scratch (no allocations allowed) ----------------
__device__ float g_eu[BB*KK];
__device__ float g_ev[BB*KK];
__device__ float g_ot[BB];
__device__ float g_ce[BB];
__device__ float g_soff[BB];
__device__ float g_sdiag[BB];
__device__ unsigned g_errslot[MAXIT];
__device__ unsigned g_cntslot[MAXIT];

// ---------------- block reduction helpers ----------------
__device__ __forceinline__ float warpMax(float v){
#pragma unroll
    for (int o = 16; o; o >>= 1) v = fmaxf(v, __shfl_xor_sync(0xffffffffu, v, o));
    return v;
}
__device__ __forceinline__ float warpSum(float v){
#pragma unroll
    for (int o = 16; o; o >>= 1) v += __shfl_xor_sync(0xffffffffu, v, o);
    return v;
}
__device__ __forceinline__ float blkMax(float v, float* red){
    int t = threadIdx.x;
    v = warpMax(v);
    if ((t & 31) == 0) red[t >> 5] = v;
    __syncthreads();
    if (t == 0){
        float r = red[0];
#pragma unroll
        for (int w = 1; w < NTHR/32; w++) r = fmaxf(r, red[w]);
        red[8] = r;
    }
    __syncthreads();
    float r = red[8];
    __syncthreads();            // protect red for next use
    return r;
}
__device__ __forceinline__ float blkSum(float v, float* red){
    int t = threadIdx.x;
    v = warpSum(v);
    if ((t & 31) == 0) red[t >> 5] = v;
    __syncthreads();
    if (t == 0){
        float r = red[0];
#pragma unroll
        for (int w = 1; w < NTHR/32; w++) r += red[w];
        red[8] = r;
    }
    __syncthreads();
    float r = red[8];
    __syncthreads();
    return r;
}

// ---------------- kernel 0: reset cross-block sync state ----------------
__global__ void reset_kernel(){
    int t = threadIdx.x;
    if (t < MAXIT){ g_errslot[t] = 0u; g_cntslot[t] = 0u; }
}

// ---------------- kernel 1: persistent Sinkhorn (one block per batch row) --
__global__ void __launch_bounds__(NTHR) sinkhorn_kernel(
    const float* __restrict__ SL, const float* __restrict__ TL,
    const int* __restrict__ labels)
{
    __shared__ float la[KK], lb[KK], f[KK], g[KK];
    __shared__ float red[9];
    __shared__ unsigned sh_done;

    const int b = blockIdx.x, t = threadIdx.x;
    const float* sl = SL + b*KK;
    const float* tl = TL + b*KK;
    const float LOGC = -18.420680743952367f;      // log(1e-8)
    const float LAM  = 2.0611536224385579e-09f;   // exp(-20)

    // teacher log-probs at TEMP=4, clamped
    float m = -1e30f;
    for (int j=t; j<KK; j+=NTHR) m = fmaxf(m, tl[j]*0.25f);
    m = blkMax(m, red);
    float s = 0.f;
    for (int j=t; j<KK; j+=NTHR) s += __expf(tl[j]*0.25f - m);
    s = blkSum(s, red);
    float lz = __logf(s);
    for (int j=t; j<KK; j+=NTHR) la[j] = fmaxf(tl[j]*0.25f - m - lz, LOGC);

    // student log-probs at TEMP=4, clamped
    m = -1e30f;
    for (int j=t; j<KK; j+=NTHR) m = fmaxf(m, sl[j]*0.25f);
    m = blkMax(m, red);
    s = 0.f;
    for (int j=t; j<KK; j+=NTHR) s += __expf(sl[j]*0.25f - m);
    s = blkSum(s, red);
    lz = __logf(s);
    for (int j=t; j<KK; j+=NTHR) lb[j] = fmaxf(sl[j]*0.25f - m - lz, LOGC);

    for (int j=t; j<KK; j+=NTHR){ f[j] = 0.f; g[j] = 0.f; }
    __syncthreads();

    // Sinkhorn loop with exact global-done semantics
    for (int it = 0; it < MAXIT; ++it){
        // f update:  f_i = -(m1 + log(e_i + LAM*(S1 - e_i))),  e = exp(g+lb-m1)
        float m1 = -1e30f;
        for (int j=t; j<KK; j+=NTHR) m1 = fmaxf(m1, g[j] + lb[j]);
        m1 = blkMax(m1, red);
        float s1 = 0.f;
        for (int j=t; j<KK; j+=NTHR) s1 += __expf(g[j] + lb[j] - m1);
        s1 = blkSum(s1, red);
        float errl = 0.f;
        for (int j=t; j<KK; j+=NTHR){
            float e  = __expf(g[j] + lb[j] - m1);
            float fn = -(m1 + __logf(fmaf(LAM, s1 - e, e)));
            errl = fmaxf(errl, fabsf(fn - f[j]));
            f[j] = fn;
        }
        __syncthreads();
        float err = blkMax(errl, red);

        // g update with new f
        float m2 = -1e30f;
        for (int j=t; j<KK; j+=NTHR) m2 = fmaxf(m2, f[j] + la[j]);
        m2 = blkMax(m2, red);
        float s2 = 0.f;
        for (int j=t; j<KK; j+=NTHR) s2 += __expf(f[j] + la[j] - m2);
        s2 = blkSum(s2, red);
        for (int j=t; j<KK; j+=NTHR){
            float e = __expf(f[j] + la[j] - m2);
            g[j] = -(m2 + __logf(fmaf(LAM, s2 - e, e)));
        }
        __syncthreads();

        // global max-err exchange (all 64 blocks co-resident: grid < #SMs)
        if (t == 0){
            atomicMax(&g_errslot[it], __float_as_uint(err)); // err >= 0: uint order == float order
            __threadfence();
            atomicAdd(&g_cntslot[it], 1u);
            while (*(volatile unsigned*)&g_cntslot[it] < BB) { }
            __threadfence();
            unsigned eb = *(volatile unsigned*)&g_errslot[it];
            sh_done = (__uint_as_float(eb) < 1e-3f) ? 1u : 0u;
        }
        __syncthreads();
        if (sh_done) break;   // identical decision in every block
    }

    // epilogue: factorized pi = exp(u_i-cu)*exp(v_j-cv)*exp(cu+cv-M)
    float cul = -1e30f, cvl = -1e30f;
    for (int j=t; j<KK; j+=NTHR){
        cul = fmaxf(cul, f[j] + la[j]);
        cvl = fmaxf(cvl, g[j] + lb[j]);
    }
    float cu = blkMax(cul, red);
    float cv = blkMax(cvl, red);
    float Sul = 0.f, Svl = 0.f, Dl = 0.f;
    for (int j=t; j<KK; j+=NTHR){
        float eu = __expf(f[j] + la[j] - cu);
        float ev = __expf(g[j] + lb[j] - cv);
        g_eu[b*KK + j] = eu;
        g_ev[b*KK + j] = ev;
        Sul += eu; Svl += ev; Dl += eu*ev;
    }
    float Su = blkSum(Sul, red);
    float Sv = blkSum(Svl, red);
    float D  = blkSum(Dl,  red);

    // CE at temperature 1
    float ms = -1e30f;
    for (int j=t; j<KK; j+=NTHR) ms = fmaxf(ms, sl[j]);
    ms = blkMax(ms, red);
    float zs = 0.f;
    for (int j=t; j<KK; j+=NTHR) zs += __expf(sl[j] - ms);
    zs = blkSum(zs, red);

    if (t == 0){
        float soff = __expf(cu + cv - 20.0f);   // off-diagonal scale (cu+cv <= 20, finite)
        g_soff[b]  = soff;
        g_sdiag[b] = __expf(cu + cv);           // diagonal scale
        g_ot[b] = soff * (Su*Sv - D);           // sum_{i!=j} pi_ij
        g_ce[b] = -(sl[labels[b]] - (ms + __logf(zs)));
    }
}

// ---------------- kernel 2: deterministic finalize ----------------
__global__ void finalize_kernel(float* __restrict__ out){
    int t = threadIdx.x; // 64 threads
    float ot = g_ot[t], ce = g_ce[t];
    __shared__ float sot[2], sce[2];
    ot = warpSum(ot); ce = warpSum(ce);
    if ((t & 31) == 0){ sot[t>>5] = ot; sce[t>>5] = ce; }
    __syncthreads();
    if (t == 0){
        float OT = (sot[0] + sot[1]) * (1.0f/64.0f);
        float CE = (sce[0] + sce[1]) * (1.0f/64.0f);
        out[0] = CE + 0.5f*OT;   // total_loss
        out[1] = OT;             // ot_loss
        out[2] = CE;             // ce_loss
    }
}

// ---------------- kernel 3: transport plan writer (HBM-bound) ----------------
__global__ void __launch_bounds__(NTHR) plan_kernel(float* __restrict__ outp){
    __shared__ float evs[KK];
    __shared__ float sR;
    const int blk = blockIdx.x;
    const int b   = blk / (KK/ROWS_PER);
    const int i0  = (blk % (KK/ROWS_PER)) * ROWS_PER;
    const int t   = threadIdx.x;

    float soff = g_soff[b];
    if (t == 0) sR = g_sdiag[b] / soff;        // e^20 up to 1 ulp
    for (int j=t; j<KK; j+=NTHR) evs[j] = g_ev[b*KK + j] * soff;
    __syncthreads();
    const float R = sR;

#pragma unroll
    for (int r = 0; r < ROWS_PER; r++){
        int i = i0 + r;
        float eu = g_eu[b*KK + i];
        float* p = outp + (size_t)(b*KK + i) * KK;   // (base+3 floats) + row*1000 -> p+1 is 16B aligned
        if (t == 0){
            float v = eu * evs[0];
            if (i == 0) v *= R;
            p[0] = v;
        }
        if (t < 249){
            int j0 = 1 + 4*t;
            float4 v;
            v.x = eu * evs[j0+0];
            v.y = eu * evs[j0+1];
            v.z = eu * evs[j0+2];
            v.w = eu * evs[j0+3];
            if (i >= j0 && i < j0+4) ((float*)&v)[i - j0] *= R;  // diagonal fixup
            *reinterpret_cast<float4*>(p + j0) = v;
        } else if (t < 252){
            int j = 997 + (t - 249);
            float v = eu * evs[j];
            if (j == i) v *= R;
            p[j] = v;
        }
    }
}

// ---------------- launch ----------------
extern "C" void kernel_launch(void* const* d_in, const int* in_sizes, int n_in,
                              void* d_out, int out_size)
{
    const float* sl     = (const float*)d_in[0];  // student_logits [64,1000]
    const float* tl     = (const float*)d_in[1];  // teacher_logits [64,1000]
    const int*   labels = (const int*)d_in[2];    // labels [64]
    // d_in[3] = C, structure known analytically (1 - I), unused
    float* out = (float*)d_out;                   // [3 + 64*1000*1000]

    reset_kernel<<<1, 64>>>();
    sinkhorn_kernel<<<BB, NTHR>>>(sl, tl, labels);
    finalize_kernel<<<1, 64>>>(out);
    plan_kernel<<<BB*(KK/ROWS_PER), NTHR>>>(out + 3);
}

// round 7
// speedup vs baseline: 1.5600x; 1.5600x over previous
#include <cuda_runtime.h>
#include <cstdint>

#define KK 1000
#define BB 64
#define MAXIT 50
#define NTHR_S 128
#define EPT 8            // elements per thread, 128*8 = 1024 >= 1000
#define NTHR_P 256
#define ROWS_PER 10

// ---------------- device scratch (no allocations allowed) ----------------
__device__ float g_eu[BB*KK];
__device__ float g_ev[BB*KK];
__device__ float g_ot[BB];
__device__ float g_ce[BB];
__device__ float g_soff[BB];
__device__ unsigned g_errslot[MAXIT];
__device__ unsigned g_cntslot[MAXIT];

// ---------------- fused block reduction: sum + max, ONE barrier ----------
// Parity-alternating buffers (caller toggles pb) make the single barrier safe:
// a buffer is rewritten only after an intervening barrier on the other buffer.
__device__ __forceinline__ void red_sum_max(float& s, float& m,
                                            volatile float* bs, volatile float* bm,
                                            int t){
#pragma unroll
    for (int o = 16; o; o >>= 1){
        s += __shfl_xor_sync(0xffffffffu, s, o);
        m  = fmaxf(m, __shfl_xor_sync(0xffffffffu, m, o));
    }
    if ((t & 31) == 0){ bs[t >> 5] = s; bm[t >> 5] = m; }
    __syncthreads();
    s = (bs[0] + bs[1]) + (bs[2] + bs[3]);
    m = fmaxf(fmaxf(bm[0], bm[1]), fmaxf(bm[2], bm[3]));
}

// ---------------- kernel 0: reset cross-block sync state ----------------
__global__ void reset_kernel(){
    int t = threadIdx.x;
    if (t < MAXIT){ g_errslot[t] = 0u; g_cntslot[t] = 0u; }
}

// ---------------- kernel 1: persistent Sinkhorn, register-resident ------
__global__ void __launch_bounds__(NTHR_S) sinkhorn_kernel(
    const float* __restrict__ SL, const float* __restrict__ TL,
    const int* __restrict__ labels)
{
    __shared__ float rs[2][4], rm[2][4];
    __shared__ unsigned sh_done;

    const int b = blockIdx.x, t = threadIdx.x;
    const int base = t * EPT;
    const bool valid = (base < KK);          // uniform per thread (last 3 threads are pads)
    const float* sl = SL + b*KK;
    const float* tl = TL + b*KK;

    const float LOGC = -18.420680743952367f;     // log(1e-8)
    const float LAM  = 2.0611536224385579e-09f;  // exp(-20)
    const float SH   = 20.0f;                    // fixed logsumexp shift (cost range)

    float la[EPT], lb[EPT], f[EPT], g[EPT], slr[EPT], xr[EPT];
    int pb = 0;

    // ---- teacher log-probs @ TEMP=4, clamped ----
    if (valid){
        float4 a0 = *(const float4*)(tl + base);
        float4 a1 = *(const float4*)(tl + base + 4);
        xr[0]=a0.x*0.25f; xr[1]=a0.y*0.25f; xr[2]=a0.z*0.25f; xr[3]=a0.w*0.25f;
        xr[4]=a1.x*0.25f; xr[5]=a1.y*0.25f; xr[6]=a1.z*0.25f; xr[7]=a1.w*0.25f;
    } else {
#pragma unroll
        for (int k=0;k<EPT;k++) xr[k] = -1e30f;
    }
    {
        float m = -1e30f, ds = 0.f;
#pragma unroll
        for (int k=0;k<EPT;k++) m = fmaxf(m, xr[k]);
        red_sum_max(ds, m, rs[pb], rm[pb], t); pb ^= 1;
        float s = 0.f, dm = -1e30f;
#pragma unroll
        for (int k=0;k<EPT;k++) s += __expf(xr[k] - m);
        red_sum_max(s, dm, rs[pb], rm[pb], t); pb ^= 1;
        float lz = m + __logf(s);
#pragma unroll
        for (int k=0;k<EPT;k++) la[k] = valid ? fmaxf(xr[k] - lz, LOGC) : -1e30f;
    }

    // ---- student log-probs @ TEMP=4, clamped (keep raw logits for CE) ----
    if (valid){
        float4 a0 = *(const float4*)(sl + base);
        float4 a1 = *(const float4*)(sl + base + 4);
        slr[0]=a0.x; slr[1]=a0.y; slr[2]=a0.z; slr[3]=a0.w;
        slr[4]=a1.x; slr[5]=a1.y; slr[6]=a1.z; slr[7]=a1.w;
#pragma unroll
        for (int k=0;k<EPT;k++) xr[k] = slr[k]*0.25f;
    } else {
#pragma unroll
        for (int k=0;k<EPT;k++){ slr[k] = -1e30f; xr[k] = -1e30f; }
    }
    {
        float m = -1e30f, ds = 0.f;
#pragma unroll
        for (int k=0;k<EPT;k++) m = fmaxf(m, xr[k]);
        red_sum_max(ds, m, rs[pb], rm[pb], t); pb ^= 1;
        float s = 0.f, dm = -1e30f;
#pragma unroll
        for (int k=0;k<EPT;k++) s += __expf(xr[k] - m);
        red_sum_max(s, dm, rs[pb], rm[pb], t); pb ^= 1;
        float lz = m + __logf(s);
#pragma unroll
        for (int k=0;k<EPT;k++) lb[k] = valid ? fmaxf(xr[k] - lz, LOGC) : -1e30f;
    }

#pragma unroll
    for (int k=0;k<EPT;k++){ f[k] = 0.f; g[k] = 0.f; }

    // ---- Sinkhorn loop: exact reference freeze semantics, pipelined sync ----
    for (int it = 0; it < MAXIT; ++it){
        // done-check for PREVIOUS iteration (exchange latency hidden by last
        // iteration's compute; semantics identical: err_t gates iteration t+1)
        if (it > 0){
            if (t == 0){
                while (*(volatile unsigned*)&g_cntslot[it-1] < BB) { }
                __threadfence();
                unsigned eb = *(volatile unsigned*)&g_errslot[it-1];
                sh_done = (__uint_as_float(eb) < 1e-3f) ? 1u : 0u;
            }
            __syncthreads();
            if (sh_done) break;
        }

        // f update: f_i = -(SH + log(e_i + LAM*S1)),  e = exp(g+lb-SH)
        float e1[EPT]; float s1 = 0.f;
#pragma unroll
        for (int k=0;k<EPT;k++){ e1[k] = __expf(g[k] + lb[k] - SH); s1 += e1[k]; }
        float dm = -1e30f;
        red_sum_max(s1, dm, rs[pb], rm[pb], t); pb ^= 1;
        float A1 = LAM * s1;

        float err = 0.f, s2 = 0.f; float e2[EPT];
#pragma unroll
        for (int k=0;k<EPT;k++){
            float fn = -(SH + __logf(e1[k] + A1));
            float d  = fabsf(fn - f[k]);
            if (valid) err = fmaxf(err, d);      // pads excluded from err
            f[k] = fn;
            e2[k] = __expf(fn + la[k] - SH);     // pads -> 0
            s2 += e2[k];
        }
        red_sum_max(s2, err, rs[pb], rm[pb], t); pb ^= 1;

        // fire global err exchange ASAP (consumed at top of next iteration)
        if (t == 0){
            atomicMax(&g_errslot[it], __float_as_uint(err)); // err>=0: uint order==float order
            __threadfence();
            atomicAdd(&g_cntslot[it], 1u);
        }

        // g update (thread-local only, no barrier needed)
        float A2 = LAM * s2;
#pragma unroll
        for (int k=0;k<EPT;k++) g[k] = -(SH + __logf(e2[k] + A2));
    }

    // ---- epilogue: factorized plan + ot + ce ----
    float cu = -1e30f, cv = -1e30f;
#pragma unroll
    for (int k=0;k<EPT;k++){
        cu = fmaxf(cu, f[k] + la[k]);
        cv = fmaxf(cv, g[k] + lb[k]);
    }
    { float ds=0.f; red_sum_max(ds, cu, rs[pb], rm[pb], t); pb ^= 1; }
    { float ds=0.f; red_sum_max(ds, cv, rs[pb], rm[pb], t); pb ^= 1; }

    float Su = 0.f, Sv = 0.f, D = 0.f;
    float eu[EPT], ev[EPT];
#pragma unroll
    for (int k=0;k<EPT;k++){
        eu[k] = __expf(f[k] + la[k] - cu);   // pads -> 0
        ev[k] = __expf(g[k] + lb[k] - cv);
        Su += eu[k]; Sv += ev[k]; D += eu[k]*ev[k];
    }
    if (valid){
        *(float4*)(g_eu + b*KK + base)     = make_float4(eu[0],eu[1],eu[2],eu[3]);
        *(float4*)(g_eu + b*KK + base + 4) = make_float4(eu[4],eu[5],eu[6],eu[7]);
        *(float4*)(g_ev + b*KK + base)     = make_float4(ev[0],ev[1],ev[2],ev[3]);
        *(float4*)(g_ev + b*KK + base + 4) = make_float4(ev[4],ev[5],ev[6],ev[7]);
    }
    { float dm=-1e30f; red_sum_max(Su, dm, rs[pb], rm[pb], t); pb ^= 1; }
    { float dm=-1e30f; red_sum_max(Sv, dm, rs[pb], rm[pb], t); pb ^= 1; }
    { float dm=-1e30f; red_sum_max(D,  dm, rs[pb], rm[pb], t); pb ^= 1; }

    // CE at temperature 1
    float ms = -1e30f, ds2 = 0.f;
#pragma unroll
    for (int k=0;k<EPT;k++) ms = fmaxf(ms, slr[k]);
    red_sum_max(ds2, ms, rs[pb], rm[pb], t); pb ^= 1;
    float zs = 0.f, dm2 = -1e30f;
#pragma unroll
    for (int k=0;k<EPT;k++) zs += __expf(slr[k] - ms);
    red_sum_max(zs, dm2, rs[pb], rm[pb], t); pb ^= 1;

    if (t == 0){
        float soff = __expf(cu + cv - 20.0f);   // off-diagonal scale
        g_soff[b]  = soff;
        g_ot[b]    = soff * (Su*Sv - D);        // sum_{i!=j} pi_ij
        g_ce[b]    = -(sl[labels[b]] - (ms + __logf(zs)));
    }
}

// ---------------- kernel 2: deterministic finalize ----------------
__global__ void finalize_kernel(float* __restrict__ out){
    int t = threadIdx.x; // 64 threads
    float ot = g_ot[t], ce = g_ce[t];
    __shared__ float sot[2], sce[2];
#pragma unroll
    for (int o = 16; o; o >>= 1){
        ot += __shfl_xor_sync(0xffffffffu, ot, o);
        ce += __shfl_xor_sync(0xffffffffu, ce, o);
    }
    if ((t & 31) == 0){ sot[t>>5] = ot; sce[t>>5] = ce; }
    __syncthreads();
    if (t == 0){
        float OT = (sot[0] + sot[1]) * (1.0f/64.0f);
        float CE = (sce[0] + sce[1]) * (1.0f/64.0f);
        out[0] = CE + 0.5f*OT;   // total_loss
        out[1] = OT;             // ot_loss
        out[2] = CE;             // ce_loss
    }
}

// ---------------- kernel 3: plan writer — register-resident ev, no smem ----
__global__ void __launch_bounds__(NTHR_P) plan_kernel(float* __restrict__ outp){
    const int blk = blockIdx.x;
    const int b   = blk / (KK/ROWS_PER);
    const int i0  = (blk % (KK/ROWS_PER)) * ROWS_PER;
    const int t   = threadIdx.x;

    const float soff = g_soff[b];
    const float R    = 4.85165195409790278e8f;   // e^20 : diag/offdiag ratio
    const float* __restrict__ evrow = g_ev + b*KK;
    const float* __restrict__ eurow = g_eu + b*KK;

    // Each thread's ev slice is invariant across the 10 rows -> registers.
    float4 er = make_float4(0.f,0.f,0.f,0.f);
    const int j0 = 1 + 4*t;
    if (t < 249){
        er.x = evrow[j0+0]*soff; er.y = evrow[j0+1]*soff;
        er.z = evrow[j0+2]*soff; er.w = evrow[j0+3]*soff;
    }
    float ese = 0.f; int js = -1;
    if (t >= 249 && t < 253){
        js  = (t == 252) ? 0 : (997 + (t - 249));
        ese = evrow[js]*soff;
    }

    float eus[ROWS_PER];
#pragma unroll
    for (int r = 0; r < ROWS_PER; r++) eus[r] = eurow[i0 + r];

#pragma unroll
    for (int r = 0; r < ROWS_PER; r++){
        const int i = i0 + r;
        float* p = outp + (size_t)(b*KK + i) * KK;   // (+3 floats base) + 1 -> 16B aligned at j0
        const float eu = eus[r];
        if (t < 249){
            float4 v;
            v.x = eu*er.x; v.y = eu*er.y; v.z = eu*er.z; v.w = eu*er.w;
            unsigned d = (unsigned)(i - j0);
            if (d < 4u) ((float*)&v)[d] *= R;        // diagonal fixup
            __stcs(reinterpret_cast<float4*>(p + j0), v);
        } else if (t < 253){
            float v = eu * ese;
            if (js == i) v *= R;
            __stcs(p + js, v);
        }
    }
}

// ---------------- launch ----------------
extern "C" void kernel_launch(void* const* d_in, const int* in_sizes, int n_in,
                              void* d_out, int out_size)
{
    const float* sl     = (const float*)d_in[0];  // student_logits [64,1000]
    const float* tl     = (const float*)d_in[1];  // teacher_logits [64,1000]
    const int*   labels = (const int*)d_in[2];    // labels [64]
    // d_in[3] = C, structure known analytically (1 - I), unused
    float* out = (float*)d_out;                   // [3 + 64*1000*1000]

    reset_kernel<<<1, 64>>>();
    sinkhorn_kernel<<<BB, NTHR_S>>>(sl, tl, labels);
    finalize_kernel<<<1, 64>>>(out);
    plan_kernel<<<BB*(KK/ROWS_PER), NTHR_P>>>(out + 3);
}

// round 12
// speedup vs baseline: 2.3081x; 1.4796x over previous
#include <cuda_runtime.h>
#include <cstdint>

#define KK 1000
#define BB 64
#define MAXIT 50
#define NBLK_S 16
#define ROWS_B 4          // batch rows per sinkhorn block
#define NTHR_S 512
#define EPT 8             // 128 threads/row * 8 = 1024 >= 1000
#define NTHR_P 256
#define ROWS_PER 10
#define BV_STRIDE 1008    // padded row stride so (b*1008+3+1+4t) is 16B aligned

// ---------------- device scratch (no allocations allowed) ----------------
__device__ float g_A[BB*KK];            // A_i = e2_i / s2          (in [0,1])
__device__ float g_Bv[BB*BV_STRIDE];    // B_j = e1_j * e^20 * s2   (in [0,1]); stored at +3 offset
__device__ float g_ot[BB];
__device__ float g_ce[BB];
__device__ unsigned g_slot[MAXIT];      // packed: low16 = arrivals, high16 = converged count

// ---------------- row reduction macros (4 warps per row) -----------------
// Buffer-reuse safety: any two consecutive reduction sites use different
// buffers, so the single barrier per site is sufficient.
#define RSUM(valv, buf, outv) do {                                         \
    float _v = (valv);                                                     \
    _Pragma("unroll")                                                      \
    for (int _o=16; _o; _o>>=1) _v += __shfl_xor_sync(0xffffffffu,_v,_o);  \
    if (lane==0) buf[row][warp] = _v;                                      \
    __syncthreads();                                                       \
    outv = (buf[row][0]+buf[row][1])+(buf[row][2]+buf[row][3]);            \
} while(0)

#define RMAXR(valv, buf, outv) do {                                        \
    float _v = (valv);                                                     \
    _Pragma("unroll")                                                      \
    for (int _o=16; _o; _o>>=1) _v = fmaxf(_v,__shfl_xor_sync(0xffffffffu,_v,_o)); \
    if (lane==0) buf[row][warp] = _v;                                      \
    __syncthreads();                                                       \
    outv = fmaxf(fmaxf(buf[row][0],buf[row][1]),fmaxf(buf[row][2],buf[row][3])); \
} while(0)

// ---------------- kernel 1: persistent Sinkhorn, 4 rows/block ------------
__global__ void __launch_bounds__(NTHR_S) sinkhorn_kernel(
    const float* __restrict__ SL, const float* __restrict__ TL,
    const int* __restrict__ labels)
{
    __shared__ float bufA[ROWS_B][4], bufB[ROWS_B][4];
    __shared__ float bufMx[ROWS_B][4], bufMn[ROWS_B][4];
    __shared__ float bufC[ROWS_B][4], bufD[ROWS_B][4];
    __shared__ unsigned sh_done;

    const int t    = threadIdx.x;
    const int row  = t >> 7;          // 0..3
    const int rt   = t & 127;         // thread within row
    const int warp = rt >> 5;         // warp within row
    const int lane = t & 31;
    const int b    = blockIdx.x * ROWS_B + row;
    const int base = rt * EPT;
    const bool valid = (base < KK);   // uniform per thread; last 3 threads/row are pads
    const float* sl = SL + b*KK;
    const float* tl = TL + b*KK;

    const float LOGC = -18.420680743952367f;     // log(1e-8)
    const float LAM  = 2.0611536224385579e-09f;  // e^-20
    const float E20  = 4.85165195409790278e8f;   // e^20
    const float SH   = 20.0f;                    // fixed logsumexp shift

    // ---- setup: log-probs @ TEMP=4, clamped ----
    float x[EPT], la[EPT], lb[EPT];

    if (valid){
        float4 a0 = *(const float4*)(tl + base);
        float4 a1 = *(const float4*)(tl + base + 4);
        x[0]=a0.x*0.25f; x[1]=a0.y*0.25f; x[2]=a0.z*0.25f; x[3]=a0.w*0.25f;
        x[4]=a1.x*0.25f; x[5]=a1.y*0.25f; x[6]=a1.z*0.25f; x[7]=a1.w*0.25f;
    } else {
#pragma unroll
        for (int k=0;k<EPT;k++) x[k] = -1e30f;
    }
    {
        float m = x[0], s;
#pragma unroll
        for (int k=1;k<EPT;k++) m = fmaxf(m, x[k]);
        RMAXR(m, bufA, m);
        float sl_ = 0.f;
#pragma unroll
        for (int k=0;k<EPT;k++) sl_ += __expf(x[k]-m);
        RSUM(sl_, bufB, s);
        float lz = m + __logf(s);
#pragma unroll
        for (int k=0;k<EPT;k++) la[k] = valid ? fmaxf(x[k]-lz, LOGC) : -1e30f;
    }
    if (valid){
        float4 a0 = *(const float4*)(sl + base);
        float4 a1 = *(const float4*)(sl + base + 4);
        x[0]=a0.x*0.25f; x[1]=a0.y*0.25f; x[2]=a0.z*0.25f; x[3]=a0.w*0.25f;
        x[4]=a1.x*0.25f; x[5]=a1.y*0.25f; x[6]=a1.z*0.25f; x[7]=a1.w*0.25f;
    }
    {
        float m = x[0], s;
#pragma unroll
        for (int k=1;k<EPT;k++) m = fmaxf(m, x[k]);
        RMAXR(m, bufA, m);
        float sl_ = 0.f;
#pragma unroll
        for (int k=0;k<EPT;k++) sl_ += __expf(x[k]-m);
        RSUM(sl_, bufB, s);
        float lz = m + __logf(s);
#pragma unroll
        for (int k=0;k<EPT;k++) lb[k] = valid ? fmaxf(x[k]-lz, LOGC) : -1e30f;
    }

    // state: e1 = exp(g+lb-SH), e2 = exp(f+la-SH); P,Q folded exponentials
    float P[EPT], Q[EPT], e1[EPT], e2[EPT], inv1p[EPT];
#pragma unroll
    for (int k=0;k<EPT;k++){
        Q[k]     = __expf(la[k] - 2.f*SH);    // la-40 >= -65 -> normal
        P[k]     = __expf(lb[k] - 2.f*SH);
        e1[k]    = __expf(lb[k] - SH);        // g=0 init
        inv1p[k] = E20;                       // 1/w1_old with f_old=0 -> w1_old=e^-SH
    }

    // ---- Sinkhorn loop: exact reference freeze semantics, pipelined sync ----
    float s2 = 0.f;
    for (int it = 0; it < MAXIT; ++it){
        // t0 polls PREVIOUS iteration's packed slot while others compute
        if (t == 0 && it > 0){
            unsigned v;
            do { v = *(volatile unsigned*)&g_slot[it-1]; }
            while ((v & 0xFFFFu) < (unsigned)NBLK_S);
            sh_done = (v >> 16);
        }
        float s1l = ((e1[0]+e1[1])+(e1[2]+e1[3]))+((e1[4]+e1[5])+(e1[6]+e1[7]));
        float s1;
        RSUM(s1l, bufA, s1);                         // barrier also publishes sh_done
        if (it > 0 && sh_done == (unsigned)NBLK_S) break;  // frozen at state of it-1

        // f-step: w1 = e1 + LAM*s1; e2 = Q/w1; ratio r tracks |f_new - f_old|
        float A1 = LAM * s1;
        float s2l = 0.f, rmx = 0.f, rmn = 1e30f;
#pragma unroll
        for (int k=0;k<EPT;k++){
            float w1  = e1[k] + A1;
            float inv = __fdividef(1.f, w1);
            float e2k = Q[k] * inv;
            float r   = w1 * inv1p[k];        // w1_new / w1_old
            inv1p[k]  = inv;
            e2[k]     = e2k;
            s2l      += e2k;
            rmx = fmaxf(rmx, r);
            rmn = fminf(rmn, r);
        }
        if (!valid){ rmx = 1.f; rmn = 1.f; }  // pads excluded from err

        // fused triple reduce: sum + max + min
#pragma unroll
        for (int o=16;o;o>>=1){
            s2l += __shfl_xor_sync(0xffffffffu, s2l, o);
            rmx  = fmaxf(rmx, __shfl_xor_sync(0xffffffffu, rmx, o));
            rmn  = fminf(rmn, __shfl_xor_sync(0xffffffffu, rmn, o));
        }
        if (lane==0){ bufB[row][warp]=s2l; bufMx[row][warp]=rmx; bufMn[row][warp]=rmn; }
        __syncthreads();
        s2 = (bufB[row][0]+bufB[row][1])+(bufB[row][2]+bufB[row][3]);

        // t0: block err over all 4 rows (16 warp partials), ONE packed atomic
        if (t == 0){
            float RX = ((float*)bufMx)[0], RN = ((float*)bufMn)[0];
#pragma unroll
            for (int i=1;i<ROWS_B*4;i++){
                RX = fmaxf(RX, ((float*)bufMx)[i]);
                RN = fminf(RN, ((float*)bufMn)[i]);
            }
            float err = fmaxf(fabsf(__logf(RX)), fabsf(__logf(RN)));
            atomicAdd(&g_slot[it], 1u + ((err < 1e-3f) ? 0x10000u : 0u));
        }

        // g-step: e1 = P / (e2 + LAM*s2)   (no barrier needed)
        float A2 = LAM * s2;
#pragma unroll
        for (int k=0;k<EPT;k++){
            float w2 = e2[k] + A2;
            e1[k] = P[k] * __fdividef(1.f, w2);
        }
    }

    // ---- epilogue ----
    // s2 corresponds to final f's e2; e1 corresponds to final g.  pi_off = e2_i*e1_j*e^20.
    float s1fl = 0.f, El = 0.f;
#pragma unroll
    for (int k=0;k<EPT;k++){ s1fl += e1[k]; El += e1[k]*e2[k]; }
#pragma unroll
    for (int o=16;o;o>>=1){
        s1fl += __shfl_xor_sync(0xffffffffu, s1fl, o);
        El   += __shfl_xor_sync(0xffffffffu, El,   o);
    }
    if (lane==0){ bufC[row][warp]=s1fl; bufD[row][warp]=El; }
    __syncthreads();
    float s1f = (bufC[row][0]+bufC[row][1])+(bufC[row][2]+bufC[row][3]);
    float E   = (bufD[row][0]+bufD[row][1])+(bufD[row][2]+bufD[row][3]);

    // factors: A = e2/s2 (<=1), B = e1*e^20*s2 (<=1); A*B = off-diag pi, diag *e^20
    float rs2 = __fdividef(1.f, s2);
    float cB  = E20 * s2;
    if (valid){
        float* pa = g_A + b*KK + base;
        *(float4*)(pa)   = make_float4(e2[0]*rs2, e2[1]*rs2, e2[2]*rs2, e2[3]*rs2);
        *(float4*)(pa+4) = make_float4(e2[4]*rs2, e2[5]*rs2, e2[6]*rs2, e2[7]*rs2);
        float* pb = g_Bv + b*BV_STRIDE + 3 + base;   // +3 mirrors output misalignment
#pragma unroll
        for (int k=0;k<EPT;k++) pb[k] = e1[k]*cB;
    }

    // CE at temperature 1 (reload raw logits; still L2-resident)
    if (valid){
        float4 a0 = *(const float4*)(sl + base);
        float4 a1 = *(const float4*)(sl + base + 4);
        x[0]=a0.x; x[1]=a0.y; x[2]=a0.z; x[3]=a0.w;
        x[4]=a1.x; x[5]=a1.y; x[6]=a1.z; x[7]=a1.w;
    } else {
#pragma unroll
        for (int k=0;k<EPT;k++) x[k] = -1e30f;
    }
    float ms = x[0], zs;
#pragma unroll
    for (int k=1;k<EPT;k++) ms = fmaxf(ms, x[k]);
    RMAXR(ms, bufB, ms);
    float zl = 0.f;
#pragma unroll
    for (int k=0;k<EPT;k++) zl += __expf(x[k]-ms);
    RSUM(zl, bufA, zs);

    if (rt == 0){
        g_ot[b] = E20 * (s1f*s2 - E);   // e^20*(Σe1*Σe2 − Σe1e2) = off-diag mass
        g_ce[b] = -(sl[labels[b]] - ms - __logf(zs));
    }
}

// ---------------- kernel 2: plan writer + finalize + slot reset ----------
__global__ void __launch_bounds__(NTHR_P, 8) planfin_kernel(float* __restrict__ out)
{
    float* __restrict__ outp = out + 3;
    const int blk = blockIdx.x;
    const int b   = blk / (KK/ROWS_PER);
    const int i0  = (blk % (KK/ROWS_PER)) * ROWS_PER;
    const int t   = threadIdx.x;
    const float R = 4.85165195409790278e8f;   // e^20 diagonal fixup

    if (blk == 0){
        if (t < MAXIT) g_slot[t] = 0u;        // reset sync state for next replay
        if (t >= 64 && t < 96){               // warp 2: finalize losses
            int l = t - 64;
            float ot = g_ot[l] + g_ot[l+32];
            float ce = g_ce[l] + g_ce[l+32];
#pragma unroll
            for (int o=16;o;o>>=1){
                ot += __shfl_xor_sync(0xffffffffu, ot, o);
                ce += __shfl_xor_sync(0xffffffffu, ce, o);
            }
            if (l == 0){
                float OT = ot * (1.0f/64.0f);
                float CE = ce * (1.0f/64.0f);
                out[0] = CE + 0.5f*OT;   // total_loss
                out[1] = OT;             // ot_loss
                out[2] = CE;             // ce_loss
            }
        }
    }

    const float* __restrict__ evr = g_Bv + b*BV_STRIDE + 3;   // B_j at j, 16B aligned at j0
    const float* __restrict__ eur = g_A  + b*KK;

    // per-thread invariant ev slice in registers
    float4 er = make_float4(0.f,0.f,0.f,0.f);
    const int j0 = 1 + 4*t;
    if (t < 249) er = *(const float4*)(evr + j0);
    float ese = 0.f; int js = -1;
    if (t >= 249 && t < 253){
        js  = (t == 252) ? 0 : (997 + (t - 249));
        ese = evr[js];
    }

#pragma unroll
    for (int r = 0; r < ROWS_PER; r++){
        const int i = i0 + r;
        const float eu = eur[i];                       // uniform broadcast load
        float* p = outp + (size_t)(b*KK + i) * KK;     // p+j0 is 16B aligned
        if (t < 249){
            float4 v;
            v.x = eu*er.x; v.y = eu*er.y; v.z = eu*er.z; v.w = eu*er.w;
            unsigned d = (unsigned)(i - j0);
            if (d < 4u) ((float*)&v)[d] *= R;          // diagonal fixup
            __stcs(reinterpret_cast<float4*>(p + j0), v);
        } else if (t < 253){
            float v = eu * ese;
            if (js == i) v *= R;
            __stcs(p + js, v);
        }
    }
}

// ---------------- launch ----------------
extern "C" void kernel_launch(void* const* d_in, const int* in_sizes, int n_in,
                              void* d_out, int out_size)
{
    const float* sl     = (const float*)d_in[0];  // student_logits [64,1000]
    const float* tl     = (const float*)d_in[1];  // teacher_logits [64,1000]
    const int*   labels = (const int*)d_in[2];    // labels [64]
    // d_in[3] = C, structure known analytically (1 - I), unused
    float* out = (float*)d_out;                   // [3 + 64*1000*1000]

    sinkhorn_kernel<<<NBLK_S, NTHR_S>>>(sl, tl, labels);
    planfin_kernel<<<BB*(KK/ROWS_PER), NTHR_P>>>(out);
}

// round 15
// speedup vs baseline: 2.7828x; 1.2056x over previous
#include <cuda_runtime.h>
#include <cstdint>

#define KK 1000
#define BB 64
#define MAXIT 50
#define NBLK_S 64         // one batch row per block (64 < 148 SMs: all co-resident)
#define NTHR_S 128
#define EPT 8             // 128 threads * 8 = 1024 >= 1000
#define NTHR_P 256
#define ROWS_PER 10
#define BV_STRIDE 1008    // padded row stride so (b*1008+3+1+4t) is 16B aligned

// ---------------- device scratch (no allocations allowed) ----------------
__device__ float g_A[BB*KK];            // A_i = e2_i / s2          (in [0,1])
__device__ float g_Bv[BB*BV_STRIDE];    // B_j = e1_j * e^20 * s2   (in [0,1]); stored at +3 offset
__device__ float g_ot[BB];
__device__ float g_ce[BB];
__device__ unsigned g_slot[MAXIT];      // packed: low16 = arrivals, high16 = converged count

// ---------------- block reduction macros (4 warps) -----------------------
// Buffer-reuse safety: any two consecutive reduction sites use different
// buffers, so the single barrier per site is sufficient.
#define RSUM(valv, buf, outv) do {                                         \
    float _v = (valv);                                                     \
    _Pragma("unroll")                                                      \
    for (int _o=16; _o; _o>>=1) _v += __shfl_xor_sync(0xffffffffu,_v,_o);  \
    if (lane==0) buf[warp] = _v;                                           \
    __syncthreads();                                                       \
    outv = (buf[0]+buf[1])+(buf[2]+buf[3]);                                \
} while(0)

#define RMAXR(valv, buf, outv) do {                                        \
    float _v = (valv);                                                     \
    _Pragma("unroll")                                                      \
    for (int _o=16; _o; _o>>=1) _v = fmaxf(_v,__shfl_xor_sync(0xffffffffu,_v,_o)); \
    if (lane==0) buf[warp] = _v;                                           \
    __syncthreads();                                                       \
    outv = fmaxf(fmaxf(buf[0],buf[1]),fmaxf(buf[2],buf[3]));               \
} while(0)

// ---------------- kernel 1: persistent Sinkhorn, 1 row/block -------------
__global__ void __launch_bounds__(NTHR_S) sinkhorn_kernel(
    const float* __restrict__ SL, const float* __restrict__ TL,
    const int* __restrict__ labels)
{
    __shared__ float bufA[4], bufB[4];
    __shared__ float bufMx[4], bufMn[4];
    __shared__ float bufC[4], bufD[4];
    __shared__ unsigned sh_done;

    const int t    = threadIdx.x;
    const int warp = t >> 5;
    const int lane = t & 31;
    const int b    = blockIdx.x;
    const int base = t * EPT;
    const bool valid = (base < KK);   // uniform per thread; last 3 threads are pads
    const float* sl = SL + b*KK;
    const float* tl = TL + b*KK;

    const float LOGC = -18.420680743952367f;     // log(1e-8)
    const float LAM  = 2.0611536224385579e-09f;  // e^-20
    const float E20  = 4.85165195409790278e8f;   // e^20
    const float SH   = 20.0f;                    // fixed logsumexp shift

    // ---- setup: log-probs @ TEMP=4, clamped ----
    float x[EPT], la[EPT], lb[EPT];

    if (valid){
        float4 a0 = *(const float4*)(tl + base);
        float4 a1 = *(const float4*)(tl + base + 4);
        x[0]=a0.x*0.25f; x[1]=a0.y*0.25f; x[2]=a0.z*0.25f; x[3]=a0.w*0.25f;
        x[4]=a1.x*0.25f; x[5]=a1.y*0.25f; x[6]=a1.z*0.25f; x[7]=a1.w*0.25f;
    } else {
#pragma unroll
        for (int k=0;k<EPT;k++) x[k] = -1e30f;
    }
    {
        float m = x[0], s;
#pragma unroll
        for (int k=1;k<EPT;k++) m = fmaxf(m, x[k]);
        RMAXR(m, bufA, m);
        float sl_ = 0.f;
#pragma unroll
        for (int k=0;k<EPT;k++) sl_ += __expf(x[k]-m);
        RSUM(sl_, bufB, s);
        float lz = m + __logf(s);
#pragma unroll
        for (int k=0;k<EPT;k++) la[k] = valid ? fmaxf(x[k]-lz, LOGC) : -1e30f;
    }
    if (valid){
        float4 a0 = *(const float4*)(sl + base);
        float4 a1 = *(const float4*)(sl + base + 4);
        x[0]=a0.x*0.25f; x[1]=a0.y*0.25f; x[2]=a0.z*0.25f; x[3]=a0.w*0.25f;
        x[4]=a1.x*0.25f; x[5]=a1.y*0.25f; x[6]=a1.z*0.25f; x[7]=a1.w*0.25f;
    }
    {
        float m = x[0], s;
#pragma unroll
        for (int k=1;k<EPT;k++) m = fmaxf(m, x[k]);
        RMAXR(m, bufA, m);
        float sl_ = 0.f;
#pragma unroll
        for (int k=0;k<EPT;k++) sl_ += __expf(x[k]-m);
        RSUM(sl_, bufB, s);
        float lz = m + __logf(s);
#pragma unroll
        for (int k=0;k<EPT;k++) lb[k] = valid ? fmaxf(x[k]-lz, LOGC) : -1e30f;
    }

    // state: e1 = exp(g+lb-SH), e2 = exp(f+la-SH); P,Q folded exponentials
    float P[EPT], Q[EPT], e1[EPT], e2[EPT], inv1p[EPT];
#pragma unroll
    for (int k=0;k<EPT;k++){
        Q[k]     = __expf(la[k] - 2.f*SH);    // la-40 >= -65 -> normal
        P[k]     = __expf(lb[k] - 2.f*SH);
        e1[k]    = __expf(lb[k] - SH);        // g=0 init
        inv1p[k] = E20;                       // 1/w1_old with f_old=0 -> w1_old=e^-SH
    }

    // ---- Sinkhorn loop: exact reference freeze semantics, pipelined sync ----
    float s2 = 0.f;
    for (int it = 0; it < MAXIT; ++it){
        // t0 polls PREVIOUS iteration's packed slot while others compute
        if (t == 0 && it > 0){
            unsigned v;
            do { v = *(volatile unsigned*)&g_slot[it-1]; }
            while ((v & 0xFFFFu) < (unsigned)NBLK_S);
            sh_done = (v >> 16);
        }
        float s1l = ((e1[0]+e1[1])+(e1[2]+e1[3]))+((e1[4]+e1[5])+(e1[6]+e1[7]));
        float s1;
        RSUM(s1l, bufA, s1);                         // barrier also publishes sh_done
        if (it > 0 && sh_done == (unsigned)NBLK_S) break;  // frozen at state of it-1

        // f-step: w1 = e1 + LAM*s1; e2 = Q/w1; ratio r tracks |f_new - f_old|
        float A1 = LAM * s1;
        float s2l = 0.f, rmx = 0.f, rmn = 1e30f;
#pragma unroll
        for (int k=0;k<EPT;k++){
            float w1  = e1[k] + A1;
            float inv = __fdividef(1.f, w1);
            float e2k = Q[k] * inv;
            float r   = w1 * inv1p[k];        // w1_new / w1_old
            inv1p[k]  = inv;
            e2[k]     = e2k;
            s2l      += e2k;
            rmx = fmaxf(rmx, r);
            rmn = fminf(rmn, r);
        }
        if (!valid){ rmx = 1.f; rmn = 1.f; }  // pads excluded from err

        // fused triple reduce: sum + max + min
#pragma unroll
        for (int o=16;o;o>>=1){
            s2l += __shfl_xor_sync(0xffffffffu, s2l, o);
            rmx  = fmaxf(rmx, __shfl_xor_sync(0xffffffffu, rmx, o));
            rmn  = fminf(rmn, __shfl_xor_sync(0xffffffffu, rmn, o));
        }
        if (lane==0){ bufB[warp]=s2l; bufMx[warp]=rmx; bufMn[warp]=rmn; }
        __syncthreads();
        s2 = (bufB[0]+bufB[1])+(bufB[2]+bufB[3]);

        // t0: block err over 4 warp partials, ONE packed atomic (no fence:
        // the atomic's value IS the message)
        if (t == 0){
            float RX = fmaxf(fmaxf(bufMx[0],bufMx[1]), fmaxf(bufMx[2],bufMx[3]));
            float RN = fminf(fminf(bufMn[0],bufMn[1]), fminf(bufMn[2],bufMn[3]));
            float err = fmaxf(fabsf(__logf(RX)), fabsf(__logf(RN)));
            atomicAdd(&g_slot[it], 1u + ((err < 1e-3f) ? 0x10000u : 0u));
        }

        // g-step: e1 = P / (e2 + LAM*s2)   (no barrier needed)
        float A2 = LAM * s2;
#pragma unroll
        for (int k=0;k<EPT;k++){
            float w2 = e2[k] + A2;
            e1[k] = P[k] * __fdividef(1.f, w2);
        }
    }

    // ---- epilogue ----
    // s2 corresponds to final f's e2; e1 corresponds to final g.  pi_off = e2_i*e1_j*e^20.
    float s1fl = 0.f, El = 0.f;
#pragma unroll
    for (int k=0;k<EPT;k++){ s1fl += e1[k]; El += e1[k]*e2[k]; }
#pragma unroll
    for (int o=16;o;o>>=1){
        s1fl += __shfl_xor_sync(0xffffffffu, s1fl, o);
        El   += __shfl_xor_sync(0xffffffffu, El,   o);
    }
    if (lane==0){ bufC[warp]=s1fl; bufD[warp]=El; }
    __syncthreads();
    float s1f = (bufC[0]+bufC[1])+(bufC[2]+bufC[3]);
    float E   = (bufD[0]+bufD[1])+(bufD[2]+bufD[3]);

    // factors: A = e2/s2 (<=1), B = e1*e^20*s2 (<=1); A*B = off-diag pi, diag *e^20
    float rs2 = __fdividef(1.f, s2);
    float cB  = E20 * s2;
    if (valid){
        float* pa = g_A + b*KK + base;
        *(float4*)(pa)   = make_float4(e2[0]*rs2, e2[1]*rs2, e2[2]*rs2, e2[3]*rs2);
        *(float4*)(pa+4) = make_float4(e2[4]*rs2, e2[5]*rs2, e2[6]*rs2, e2[7]*rs2);
        float* pb = g_Bv + b*BV_STRIDE + 3 + base;   // +3 mirrors output misalignment
#pragma unroll
        for (int k=0;k<EPT;k++) pb[k] = e1[k]*cB;
    }

    // CE at temperature 1 (reload raw logits; still L2-resident)
    if (valid){
        float4 a0 = *(const float4*)(sl + base);
        float4 a1 = *(const float4*)(sl + base + 4);
        x[0]=a0.x; x[1]=a0.y; x[2]=a0.z; x[3]=a0.w;
        x[4]=a1.x; x[5]=a1.y; x[6]=a1.z; x[7]=a1.w;
    } else {
#pragma unroll
        for (int k=0;k<EPT;k++) x[k] = -1e30f;
    }
    float ms = x[0], zs;
#pragma unroll
    for (int k=1;k<EPT;k++) ms = fmaxf(ms, x[k]);
    RMAXR(ms, bufB, ms);
    float zl = 0.f;
#pragma unroll
    for (int k=0;k<EPT;k++) zl += __expf(x[k]-ms);
    RSUM(zl, bufA, zs);

    if (t == 0){
        g_ot[b] = E20 * (s1f*s2 - E);   // e^20*(Σe1*Σe2 − Σe1e2) = off-diag mass
        g_ce[b] = -(sl[labels[b]] - ms - __logf(zs));
    }
}

// ---------------- kernel 2: plan writer + finalize + slot reset ----------
__global__ void __launch_bounds__(NTHR_P, 8) planfin_kernel(float* __restrict__ out)
{
    float* __restrict__ outp = out + 3;
    const int blk = blockIdx.x;
    const int b   = blk / (KK/ROWS_PER);
    const int i0  = (blk % (KK/ROWS_PER)) * ROWS_PER;
    const int t   = threadIdx.x;
    const float R = 4.85165195409790278e8f;   // e^20 diagonal fixup

    if (blk == 0){
        if (t < MAXIT) g_slot[t] = 0u;        // reset sync state for next replay
        if (t >= 64 && t < 96){               // warp 2: finalize losses
            int l = t - 64;
            float ot = g_ot[l] + g_ot[l+32];
            float ce = g_ce[l] + g_ce[l+32];
#pragma unroll
            for (int o=16;o;o>>=1){
                ot += __shfl_xor_sync(0xffffffffu, ot, o);
                ce += __shfl_xor_sync(0xffffffffu, ce, o);
            }
            if (l == 0){
                float OT = ot * (1.0f/64.0f);
                float CE = ce * (1.0f/64.0f);
                out[0] = CE + 0.5f*OT;   // total_loss
                out[1] = OT;             // ot_loss
                out[2] = CE;             // ce_loss
            }
        }
    }

    const float* __restrict__ evr = g_Bv + b*BV_STRIDE + 3;   // B_j at j, 16B aligned at j0
    const float* __restrict__ eur = g_A  + b*KK;

    // per-thread invariant ev slice in registers
    float4 er = make_float4(0.f,0.f,0.f,0.f);
    const int j0 = 1 + 4*t;
    if (t < 249) er = *(const float4*)(evr + j0);
    float ese = 0.f; int js = -1;
    if (t >= 249 && t < 253){
        js  = (t == 252) ? 0 : (997 + (t - 249));
        ese = evr[js];
    }

#pragma unroll
    for (int r = 0; r < ROWS_PER; r++){
        const int i = i0 + r;
        const float eu = eur[i];                       // uniform broadcast load
        float* p = outp + (size_t)(b*KK + i) * KK;     // p+j0 is 16B aligned
        if (t < 249){
            float4 v;
            v.x = eu*er.x; v.y = eu*er.y; v.z = eu*er.z; v.w = eu*er.w;
            unsigned d = (unsigned)(i - j0);
            if (d < 4u) ((float*)&v)[d] *= R;          // diagonal fixup
            __stcs(reinterpret_cast<float4*>(p + j0), v);
        } else if (t < 253){
            float v = eu * ese;
            if (js == i) v *= R;
            __stcs(p + js, v);
        }
    }
}

// ---------------- launch ----------------
extern "C" void kernel_launch(void* const* d_in, const int* in_sizes, int n_in,
                              void* d_out, int out_size)
{
    const float* sl     = (const float*)d_in[0];  // student_logits [64,1000]
    const float* tl     = (const float*)d_in[1];  // teacher_logits [64,1000]
    const int*   labels = (const int*)d_in[2];    // labels [64]
    // d_in[3] = C, structure known analytically (1 - I), unused
    float* out = (float*)d_out;                   // [3 + 64*1000*1000]

    sinkhorn_kernel<<<NBLK_S, NTHR_S>>>(sl, tl, labels);
    planfin_kernel<<<BB*(KK/ROWS_PER), NTHR_P>>>(out);
}